// round 12
// baseline (speedup 1.0000x reference)
#include <cuda_runtime.h>
#include <cuda_fp16.h>

#define BATCH 4
#define SEQ   4096
#define EMBED 1024
#define HD    64
#define MTOT  (BATCH * SEQ)

// Prepared fp16 operands.
__device__ __half g_Xh[MTOT * EMBED];     // x rounded to fp16
__device__ __half g_Wh[128 * EMBED];      // [Wq;Wk] rounded to fp16
__device__ __half g_Qh[MTOT * HD];        // Q (pre-scaled by 0.125*log2e)
__device__ __half g_Kh[MTOT * HD];        // K row-major (V == K)

// ---------------------------------------------------------------------------
// PTX helpers
// ---------------------------------------------------------------------------
__device__ __forceinline__ unsigned su32(const void* p) {
    return (unsigned)__cvta_generic_to_shared(p);
}

#define LDSM_X4(r0,r1,r2,r3,addr) \
    asm volatile("ldmatrix.sync.aligned.m8n8.x4.shared.b16 {%0,%1,%2,%3}, [%4];" \
        : "=r"(r0),"=r"(r1),"=r"(r2),"=r"(r3) : "r"(addr))

#define LDSM_X4_T(r0,r1,r2,r3,addr) \
    asm volatile("ldmatrix.sync.aligned.m8n8.x4.trans.shared.b16 {%0,%1,%2,%3}, [%4];" \
        : "=r"(r0),"=r"(r1),"=r"(r2),"=r"(r3) : "r"(addr))

#define MMA_F16(d,a0,a1,a2,a3,b0,b1) \
    asm volatile("mma.sync.aligned.m16n8k16.row.col.f32.f16.f16.f32 " \
        "{%0,%1,%2,%3},{%4,%5,%6,%7},{%8,%9},{%0,%1,%2,%3};" \
        : "+f"((d)[0]),"+f"((d)[1]),"+f"((d)[2]),"+f"((d)[3]) \
        : "r"(a0),"r"(a1),"r"(a2),"r"(a3),"r"(b0),"r"(b1))

#define CP16(dst,src) asm volatile("cp.async.cg.shared.global [%0], [%1], 16;" :: "r"(dst),"l"(src))
#define CP_COMMIT()   asm volatile("cp.async.commit_group;")
#define CP_WAIT0()    asm volatile("cp.async.wait_group 0;")
#define CP_WAIT1()    asm volatile("cp.async.wait_group 1;")

// Byte offset inside an fp16 tile: 64 cols (128B rows), 16B-block xor swizzle.
__device__ __forceinline__ unsigned swz16(int r, int c8) {
    return (unsigned)(r * 128 + ((((c8 >> 3) ^ r) & 7) << 4) + ((c8 & 7) << 1));
}
// ldmatrix.x4 address: A fragment (m16 x k16) at (row_base, k-chunk t)
__device__ __forceinline__ unsigned a_addr(unsigned base, int row_base, int t, int lane) {
    int row = row_base + (lane & 15);
    int ch  = 2 * t + (lane >> 4);
    return base + row * 128 + (((ch ^ row) & 7) << 4);
}
// ldmatrix.x4 address: two B n8 tiles at n0, n0+8, k-chunk t (tile holds B^T rows=n).
__device__ __forceinline__ unsigned b_addr(unsigned base, int n0, int t, int lane) {
    int row = n0 + ((lane >> 4) << 3) + (lane & 7);
    int ch  = 2 * t + ((lane >> 3) & 1);
    return base + row * 128 + (((ch ^ row) & 7) << 4);
}
// trans B fragment for PV: rows = k (keys), cols = n (dims).
__device__ __forceinline__ unsigned bt_addr(unsigned base, int t, int p, int lane) {
    int row = 16 * t + (lane & 15);
    int c8  = 16 * p + ((lane >> 4) << 3);
    return base + swz16(row, c8);
}
__device__ __forceinline__ unsigned packh2(float a, float b) {
    __half2 h = __floats2half2_rn(a, b);
    return *(unsigned*)&h;
}

// ---------------------------------------------------------------------------
// f32 -> fp16 rounding pass. Memory-bound.
// ---------------------------------------------------------------------------
__global__ __launch_bounds__(256)
void round_kernel(const float* __restrict__ in, __half* __restrict__ h, int n4) {
    int i = blockIdx.x * blockDim.x + threadIdx.x;
    if (i >= n4) return;
    float4 v = ((const float4*)in)[i];
    ((uint2*)h)[i] = make_uint2(packh2(v.x, v.y), packh2(v.z, v.w));
}

// ---------------------------------------------------------------------------
// Projection: out[16384 x 128] = Xh @ Wh^T  (pure fp16 GEMM).
// Grid 256: (row-block 128) x (n-half 64). 256 threads, 8 warps x m16.
// ---------------------------------------------------------------------------
__global__ __launch_bounds__(256)
void proj_kernel() {
    extern __shared__ char sm[];
    const unsigned smb = su32(sm);

    const int tid = threadIdx.x, lane = tid & 31, w = tid >> 5;
    const int g = lane >> 2, t4 = lane & 3;
    const int row0 = (blockIdx.x >> 1) * 128;
    const int n0   = (blockIdx.x & 1) * 64;

    const unsigned STAGE = 24576u;   // Xh 16KB + Wh 8KB

    auto issue = [&](int kt, int st) {
        unsigned sb = smb + (unsigned)st * STAGE;
        #pragma unroll
        for (int i = 0; i < 6; ++i) {
            int lin = tid + i * 256;          // 0..1535
            if (lin < 1024) {
                int r = lin >> 3, c8 = (lin & 7) << 3;
                CP16(sb + swz16(r, c8),
                     g_Xh + (size_t)(row0 + r) * EMBED + kt * 64 + c8);
            } else {
                int q = lin - 1024; int r = q >> 3, c8 = (q & 7) << 3;
                CP16(sb + 16384u + swz16(r, c8),
                     g_Wh + (size_t)(n0 + r) * EMBED + kt * 64 + c8);
            }
        }
        CP_COMMIT();
    };

    float acc[8][4];
    #pragma unroll
    for (int j = 0; j < 8; ++j)
        #pragma unroll
        for (int q = 0; q < 4; ++q) acc[j][q] = 0.f;

    issue(0, 0);
    issue(1, 1);

    for (int kt = 0; kt < 16; ++kt) {
        if (kt < 15) { CP_WAIT1(); } else { CP_WAIT0(); }
        __syncthreads();
        if (kt + 2 < 16) issue(kt + 2, (kt + 2) % 3);

        unsigned sb = smb + (unsigned)(kt % 3) * STAGE;
        const unsigned xh_b = sb, wh_b = sb + 16384;

        #pragma unroll
        for (int t = 0; t < 4; ++t) {
            unsigned xa0,xa1,xa2,xa3;
            LDSM_X4(xa0,xa1,xa2,xa3, a_addr(xh_b, w * 16, t, lane));
            #pragma unroll
            for (int p = 0; p < 4; ++p) {
                unsigned h0,h1,h2,h3;
                LDSM_X4(h0,h1,h2,h3, b_addr(wh_b, 16 * p, t, lane));
                MMA_F16(acc[2*p],   xa0,xa1,xa2,xa3, h0,h1);
                MMA_F16(acc[2*p+1], xa0,xa1,xa2,xa3, h2,h3);
            }
        }
    }

    // Epilogue. n-half 0 -> Q (scaled by 0.125*log2e for exp2 softmax); 1 -> K.
    const float QS = 0.125f * 1.44269504f;
    const int r0g = row0 + w * 16 + g;
    if (n0 == 0) {
        #pragma unroll
        for (int j = 0; j < 8; ++j) {
            int n = 8 * j + t4 * 2;
            *(unsigned*)&g_Qh[(size_t)r0g * HD + n] =
                packh2(acc[j][0] * QS, acc[j][1] * QS);
            *(unsigned*)&g_Qh[(size_t)(r0g + 8) * HD + n] =
                packh2(acc[j][2] * QS, acc[j][3] * QS);
        }
    } else {
        #pragma unroll
        for (int j = 0; j < 8; ++j) {
            int n = 8 * j + t4 * 2;
            *(unsigned*)&g_Kh[(size_t)r0g * HD + n] = packh2(acc[j][0], acc[j][1]);
            *(unsigned*)&g_Kh[(size_t)(r0g + 8) * HD + n] = packh2(acc[j][2], acc[j][3]);
        }
    }
}

// ---------------------------------------------------------------------------
// Flash attention, fixed-shift softmax, one-iter skew with a REAL prefetch
// pipeline: issue K(jt+2) BEFORE waiting, wait_group 1 (K(jt+1) landed,
// K(jt+2) stays in flight), 4 K buffers so the early issue has no WAR hazard.
//   iter jt: issue K(jt+2) -> wait K(jt+1) -> sync -> S(jt+1) -> PV(jt) -> exp(jt+1)
// ---------------------------------------------------------------------------
__global__ __launch_bounds__(128, 2)
void attn_kernel(float* __restrict__ out) {
    extern __shared__ char sm[];
    char* Qh = sm;                 // 8KB
    char* KB = sm + 8192;          // 4 x Kh x 8KB = 32KB

    const int tid = threadIdx.x, lane = tid & 31, w = tid >> 5;
    const int g = lane >> 2, t4 = lane & 3;

    // Balanced schedule: bid and bid+148 share an SM (classic LUT = bid%148).
    int bid = blockIdx.x, qt, b;
    if (bid >= 108 && bid < 148) {
        int s5 = bid - 108; qt = 63 - (s5 >> 2); b = s5 & 3;
    } else {
        int i = (bid < 108) ? bid : (215 - (bid - 148));
        qt = 53 - (i >> 2); b = i & 3;
    }
    const int q0 = qt * 64;

    const __half* Qhg = g_Qh + (size_t)b * SEQ * HD;
    const __half* Khg = g_Kh + (size_t)b * SEQ * HD;

    const unsigned qh_b = su32(Qh);
    const unsigned kb_base = su32(KB);

    auto issue_k = [&](int j, int st) {
        unsigned kb = kb_base + (unsigned)st * 8192u;
        #pragma unroll
        for (int i = 0; i < 4; ++i) {
            int lin = tid + i * 128;          // 0..511
            int r = lin >> 3, c8 = (lin & 7) << 3;
            CP16(kb + swz16(r, c8), Khg + (size_t)(j * 64 + r) * HD + c8);
        }
        CP_COMMIT();
    };

    float o[8][4];
    #pragma unroll
    for (int j = 0; j < 8; ++j)
        #pragma unroll
        for (int q = 0; q < 4; ++q) o[j][q] = 0.f;
    float l0 = 0.f, l1 = 0.f;

    unsigned qfh[4][4];
    unsigned pp[16];           // packed P for the CURRENT tile (carried)

    // S = Qh Kh^T for one K tile (log2-domain scores).
    auto compute_s = [&](float (&sd)[8][4], unsigned kh_b) {
        #pragma unroll
        for (int j = 0; j < 8; ++j)
            #pragma unroll
            for (int q = 0; q < 4; ++q) sd[j][q] = 0.f;
        #pragma unroll
        for (int t = 0; t < 4; ++t) {
            #pragma unroll
            for (int p = 0; p < 4; ++p) {
                unsigned h0,h1,h2,h3;
                LDSM_X4(h0,h1,h2,h3, b_addr(kh_b, 16 * p, t, lane));
                MMA_F16(sd[2*p],   qfh[t][0],qfh[t][1],qfh[t][2],qfh[t][3], h0,h1);
                MMA_F16(sd[2*p+1], qfh[t][0],qfh[t][1],qfh[t][2],qfh[t][3], h2,h3);
            }
        }
    };
    // Causal mask (diagonal tile only).
    auto mask_s = [&](float (&sd)[8][4]) {
        const int r0g = w * 16 + g;
        #pragma unroll
        for (int j = 0; j < 8; ++j) {
            int c = 8 * j + t4 * 2;
            if (c     > r0g)     sd[j][0] = -1e30f;
            if (c + 1 > r0g)     sd[j][1] = -1e30f;
            if (c     > r0g + 8) sd[j][2] = -1e30f;
            if (c + 1 > r0g + 8) sd[j][3] = -1e30f;
        }
    };
    // p = exp2(s - 4); accumulate row sums; pack into pp.
    auto exp_pack = [&](float (&sd)[8][4]) {
        #pragma unroll
        for (int j = 0; j < 8; ++j) {
            sd[j][0] = exp2f(sd[j][0] - 4.f);
            sd[j][1] = exp2f(sd[j][1] - 4.f);
            sd[j][2] = exp2f(sd[j][2] - 4.f);
            sd[j][3] = exp2f(sd[j][3] - 4.f);
            l0 += sd[j][0] + sd[j][1];
            l1 += sd[j][2] + sd[j][3];
        }
        #pragma unroll
        for (int t = 0; t < 4; ++t) {
            pp[4*t+0] = packh2(sd[2*t][0],   sd[2*t][1]);
            pp[4*t+1] = packh2(sd[2*t][2],   sd[2*t][3]);
            pp[4*t+2] = packh2(sd[2*t+1][0], sd[2*t+1][1]);
            pp[4*t+3] = packh2(sd[2*t+1][2], sd[2*t+1][3]);
        }
    };
    // O += P(pp) . V  from the row-major K tile via trans ldmatrix.
    auto pv = [&](unsigned kh_b) {
        #pragma unroll
        for (int t = 0; t < 4; ++t) {
            #pragma unroll
            for (int p = 0; p < 4; ++p) {
                unsigned h0,h1,h2,h3;
                LDSM_X4_T(h0,h1,h2,h3, bt_addr(kh_b, t, p, lane));
                MMA_F16(o[2*p],   pp[4*t+0],pp[4*t+1],pp[4*t+2],pp[4*t+3], h0,h1);
                MMA_F16(o[2*p+1], pp[4*t+0],pp[4*t+1],pp[4*t+2],pp[4*t+3], h2,h3);
            }
        }
    };

    // ---- Prologue: commit {Qh,K0}; commit {K1}; wait group0 only ----
    #pragma unroll
    for (int i = 0; i < 4; ++i) {
        int lin = tid + i * 128;
        int r = lin >> 3, c8 = (lin & 7) << 3;
        CP16(qh_b + swz16(r, c8), Qhg + (size_t)(q0 + r) * HD + c8);
    }
    #pragma unroll
    for (int i = 0; i < 4; ++i) {
        int lin = tid + i * 128;
        int r = lin >> 3, c8 = (lin & 7) << 3;
        CP16(kb_base + swz16(r, c8), Khg + (size_t)r * HD + c8);
    }
    CP_COMMIT();
    if (qt >= 1) { issue_k(1, 1); CP_WAIT1(); } else { CP_WAIT0(); }
    __syncthreads();

    #pragma unroll
    for (int t = 0; t < 4; ++t)
        LDSM_X4(qfh[t][0],qfh[t][1],qfh[t][2],qfh[t][3],
                a_addr(qh_b, w * 16, t, lane));
    {
        float s0[8][4];
        compute_s(s0, kb_base);
        if (qt == 0) mask_s(s0);
        exp_pack(s0);
    }

    // ---- Main loop (skewed, depth-1 in-flight prefetch, 4 buffers) ----
    for (int jt = 0; jt <= qt; ++jt) {
        const bool more = (jt < qt);
        // Early issue: buffer (jt+2)&3 was last read at iter jt-2 (fenced by
        // the sync at iter jt-1), so no WAR hazard.
        if (jt + 2 <= qt) issue_k(jt + 2, (jt + 2) & 3);
        if (more) { CP_WAIT1(); } else { CP_WAIT0(); }
        __syncthreads();         // K(jt+1) visible; all warps past PV(jt-1)

        float sn[8][4];
        if (more) {              // S for NEXT tile (independent of pp)
            compute_s(sn, kb_base + (unsigned)((jt + 1) & 3) * 8192u);
            if (jt + 1 == qt) mask_s(sn);
        }

        pv(kb_base + (unsigned)(jt & 3) * 8192u);   // PV for CURRENT tile

        if (more) exp_pack(sn);  // EX2 overlaps PV tail / next iter's front
    }

    // ---- Epilogue: one reduction of l across the quad, then normalize ----
    l0 += __shfl_xor_sync(0xffffffffu, l0, 1);
    l0 += __shfl_xor_sync(0xffffffffu, l0, 2);
    l1 += __shfl_xor_sync(0xffffffffu, l1, 1);
    l1 += __shfl_xor_sync(0xffffffffu, l1, 2);
    float il0 = 1.f / l0, il1 = 1.f / l1;
    const int row0 = q0 + w * 16 + g;
    #pragma unroll
    for (int j = 0; j < 8; ++j) {
        int c = 8 * j + t4 * 2;
        float* d0 = out + ((size_t)b * SEQ + row0) * HD + c;
        *(float2*)d0 = make_float2(o[j][0] * il0, o[j][1] * il0);
        *(float2*)(d0 + 8 * HD) = make_float2(o[j][2] * il1, o[j][3] * il1);
    }
}

// ---------------------------------------------------------------------------
extern "C" void kernel_launch(void* const* d_in, const int* in_sizes, int n_in,
                              void* d_out, int out_size) {
    const float* x  = (const float*)d_in[0];
    const float* Wq = (const float*)d_in[1];
    const float* Wk = (const float*)d_in[2];
    // d_in[3] (Wv) is an unused parameter in the reference model.

    __half *xh, *wh;
    cudaGetSymbolAddress((void**)&xh, g_Xh);
    cudaGetSymbolAddress((void**)&wh, g_Wh);

    round_kernel<<<MTOT * EMBED / 4 / 256, 256>>>(x, xh, MTOT * EMBED / 4);
    round_kernel<<<64, 256>>>(Wq, wh, HD * EMBED / 4);
    round_kernel<<<64, 256>>>(Wk, wh + 64 * EMBED, HD * EMBED / 4);

    const int proj_smem = 3 * 24576;            // 72KB, 3-stage
    cudaFuncSetAttribute(proj_kernel, cudaFuncAttributeMaxDynamicSharedMemorySize,
                         proj_smem);
    proj_kernel<<<2 * (MTOT / 128), 256, proj_smem>>>();

    const int attn_smem = 8192 + 4 * 8192;      // 40KB -> 2 CTAs/SM
    cudaFuncSetAttribute(attn_kernel, cudaFuncAttributeMaxDynamicSharedMemorySize,
                         attn_smem);
    attn_kernel<<<256, 128, attn_smem>>>((float*)d_out);
}

// round 13
// speedup vs baseline: 1.0941x; 1.0941x over previous
#include <cuda_runtime.h>
#include <cuda_fp16.h>

#define BATCH 4
#define SEQ   4096
#define EMBED 1024
#define HD    64
#define MTOT  (BATCH * SEQ)

// Prepared fp16 operands.
__device__ __half g_Xh[MTOT * EMBED];     // x rounded to fp16
__device__ __half g_Wh[128 * EMBED];      // [Wq;Wk] rounded to fp16
__device__ __half g_Qh[MTOT * HD];        // Q (pre-scaled by 0.125*log2e)
__device__ __half g_Kh[MTOT * HD];        // K row-major (V == K)

// ---------------------------------------------------------------------------
// PTX helpers
// ---------------------------------------------------------------------------
__device__ __forceinline__ unsigned su32(const void* p) {
    return (unsigned)__cvta_generic_to_shared(p);
}

#define LDSM_X4(r0,r1,r2,r3,addr) \
    asm volatile("ldmatrix.sync.aligned.m8n8.x4.shared.b16 {%0,%1,%2,%3}, [%4];" \
        : "=r"(r0),"=r"(r1),"=r"(r2),"=r"(r3) : "r"(addr))

#define LDSM_X4_T(r0,r1,r2,r3,addr) \
    asm volatile("ldmatrix.sync.aligned.m8n8.x4.trans.shared.b16 {%0,%1,%2,%3}, [%4];" \
        : "=r"(r0),"=r"(r1),"=r"(r2),"=r"(r3) : "r"(addr))

#define MMA_F16(d,a0,a1,a2,a3,b0,b1) \
    asm volatile("mma.sync.aligned.m16n8k16.row.col.f32.f16.f16.f32 " \
        "{%0,%1,%2,%3},{%4,%5,%6,%7},{%8,%9},{%0,%1,%2,%3};" \
        : "+f"((d)[0]),"+f"((d)[1]),"+f"((d)[2]),"+f"((d)[3]) \
        : "r"(a0),"r"(a1),"r"(a2),"r"(a3),"r"(b0),"r"(b1))

#define CP16(dst,src) asm volatile("cp.async.cg.shared.global [%0], [%1], 16;" :: "r"(dst),"l"(src))
#define CP_COMMIT()   asm volatile("cp.async.commit_group;")
#define CP_WAIT0()    asm volatile("cp.async.wait_group 0;")
#define CP_WAIT1()    asm volatile("cp.async.wait_group 1;")

// Byte offset inside an fp16 tile: 64 cols (128B rows), 16B-block xor swizzle.
__device__ __forceinline__ unsigned swz16(int r, int c8) {
    return (unsigned)(r * 128 + ((((c8 >> 3) ^ r) & 7) << 4) + ((c8 & 7) << 1));
}
// ldmatrix.x4 address: A fragment (m16 x k16) at (row_base, k-chunk t)
__device__ __forceinline__ unsigned a_addr(unsigned base, int row_base, int t, int lane) {
    int row = row_base + (lane & 15);
    int ch  = 2 * t + (lane >> 4);
    return base + row * 128 + (((ch ^ row) & 7) << 4);
}
// ldmatrix.x4 address: two B n8 tiles at n0, n0+8, k-chunk t (tile holds B^T rows=n).
__device__ __forceinline__ unsigned b_addr(unsigned base, int n0, int t, int lane) {
    int row = n0 + ((lane >> 4) << 3) + (lane & 7);
    int ch  = 2 * t + ((lane >> 3) & 1);
    return base + row * 128 + (((ch ^ row) & 7) << 4);
}
// trans B fragment for PV: rows = k (keys), cols = n (dims).
__device__ __forceinline__ unsigned bt_addr(unsigned base, int t, int p, int lane) {
    int row = 16 * t + (lane & 15);
    int c8  = 16 * p + ((lane >> 4) << 3);
    return base + swz16(row, c8);
}
__device__ __forceinline__ unsigned packh2(float a, float b) {
    __half2 h = __floats2half2_rn(a, b);
    return *(unsigned*)&h;
}

// ---------------------------------------------------------------------------
// f32 -> fp16 rounding pass. Memory-bound.
// ---------------------------------------------------------------------------
__global__ __launch_bounds__(256)
void round_kernel(const float* __restrict__ in, __half* __restrict__ h, int n4) {
    int i = blockIdx.x * blockDim.x + threadIdx.x;
    if (i >= n4) return;
    float4 v = ((const float4*)in)[i];
    ((uint2*)h)[i] = make_uint2(packh2(v.x, v.y), packh2(v.z, v.w));
}

// ---------------------------------------------------------------------------
// Projection: out[16384 x 128] = Xh @ Wh^T  (pure fp16 GEMM).
// Grid 256: (row-block 128) x (n-half 64). 256 threads, 8 warps x m16.
// ---------------------------------------------------------------------------
__global__ __launch_bounds__(256)
void proj_kernel() {
    extern __shared__ char sm[];
    const unsigned smb = su32(sm);

    const int tid = threadIdx.x, lane = tid & 31, w = tid >> 5;
    const int g = lane >> 2, t4 = lane & 3;
    const int row0 = (blockIdx.x >> 1) * 128;
    const int n0   = (blockIdx.x & 1) * 64;

    const unsigned STAGE = 24576u;   // Xh 16KB + Wh 8KB

    auto issue = [&](int kt, int st) {
        unsigned sb = smb + (unsigned)st * STAGE;
        #pragma unroll
        for (int i = 0; i < 6; ++i) {
            int lin = tid + i * 256;          // 0..1535
            if (lin < 1024) {
                int r = lin >> 3, c8 = (lin & 7) << 3;
                CP16(sb + swz16(r, c8),
                     g_Xh + (size_t)(row0 + r) * EMBED + kt * 64 + c8);
            } else {
                int q = lin - 1024; int r = q >> 3, c8 = (q & 7) << 3;
                CP16(sb + 16384u + swz16(r, c8),
                     g_Wh + (size_t)(n0 + r) * EMBED + kt * 64 + c8);
            }
        }
        CP_COMMIT();
    };

    float acc[8][4];
    #pragma unroll
    for (int j = 0; j < 8; ++j)
        #pragma unroll
        for (int q = 0; q < 4; ++q) acc[j][q] = 0.f;

    issue(0, 0);
    issue(1, 1);

    for (int kt = 0; kt < 16; ++kt) {
        if (kt < 15) { CP_WAIT1(); } else { CP_WAIT0(); }
        __syncthreads();
        if (kt + 2 < 16) issue(kt + 2, (kt + 2) % 3);

        unsigned sb = smb + (unsigned)(kt % 3) * STAGE;
        const unsigned xh_b = sb, wh_b = sb + 16384;

        #pragma unroll
        for (int t = 0; t < 4; ++t) {
            unsigned xa0,xa1,xa2,xa3;
            LDSM_X4(xa0,xa1,xa2,xa3, a_addr(xh_b, w * 16, t, lane));
            #pragma unroll
            for (int p = 0; p < 4; ++p) {
                unsigned h0,h1,h2,h3;
                LDSM_X4(h0,h1,h2,h3, b_addr(wh_b, 16 * p, t, lane));
                MMA_F16(acc[2*p],   xa0,xa1,xa2,xa3, h0,h1);
                MMA_F16(acc[2*p+1], xa0,xa1,xa2,xa3, h2,h3);
            }
        }
    }

    // Epilogue. n-half 0 -> Q (scaled by 0.125*log2e for exp2 softmax); 1 -> K.
    const float QS = 0.125f * 1.44269504f;
    const int r0g = row0 + w * 16 + g;
    if (n0 == 0) {
        #pragma unroll
        for (int j = 0; j < 8; ++j) {
            int n = 8 * j + t4 * 2;
            *(unsigned*)&g_Qh[(size_t)r0g * HD + n] =
                packh2(acc[j][0] * QS, acc[j][1] * QS);
            *(unsigned*)&g_Qh[(size_t)(r0g + 8) * HD + n] =
                packh2(acc[j][2] * QS, acc[j][3] * QS);
        }
    } else {
        #pragma unroll
        for (int j = 0; j < 8; ++j) {
            int n = 8 * j + t4 * 2;
            *(unsigned*)&g_Kh[(size_t)r0g * HD + n] = packh2(acc[j][0], acc[j][1]);
            *(unsigned*)&g_Kh[(size_t)(r0g + 8) * HD + n] = packh2(acc[j][2], acc[j][3]);
        }
    }
}

// ---------------------------------------------------------------------------
// Flash attention, fixed-shift softmax, KEY-SPLIT across 8 warps:
//   warp (w&3) = row group (m16), warp (w>>5... w>>2) = key half (32 keys).
// Each warp: S(m16 x n32) -> exp -> partial O(m16 x d64) over its key half.
// Halves summed once in the epilogue via smem. Same smem/crossbar as R10,
// double the warps/SM for latency hiding. Loop structure = R10 (best known).
// ---------------------------------------------------------------------------
__global__ __launch_bounds__(256, 2)
void attn_kernel(float* __restrict__ out) {
    extern __shared__ char sm[];
    char* Qh = sm;                 // 8KB
    char* KB = sm + 8192;          // 3 x Kh x 8KB = 24KB

    const int tid = threadIdx.x, lane = tid & 31, w = tid >> 5;
    const int g = lane >> 2, t4 = lane & 3;
    const int wg = w & 3;          // row group
    const int kh = w >> 2;         // key half (0: keys 0-31, 1: keys 32-63)

    // Balanced schedule: bid and bid+148 share an SM (classic LUT = bid%148).
    int bid = blockIdx.x, qt, b;
    if (bid >= 108 && bid < 148) {
        int s5 = bid - 108; qt = 63 - (s5 >> 2); b = s5 & 3;
    } else {
        int i = (bid < 108) ? bid : (215 - (bid - 148));
        qt = 53 - (i >> 2); b = i & 3;
    }
    const int q0 = qt * 64;

    const __half* Qhg = g_Qh + (size_t)b * SEQ * HD;
    const __half* Khg = g_Kh + (size_t)b * SEQ * HD;

    const unsigned qh_b = su32(Qh);
    const unsigned kb_base = su32(KB);

    auto issue_k = [&](int j, int st) {
        unsigned kb = kb_base + (unsigned)st * 8192u;
        #pragma unroll
        for (int i = 0; i < 2; ++i) {
            int lin = tid + i * 256;          // 0..511
            int r = lin >> 3, c8 = (lin & 7) << 3;
            CP16(kb + swz16(r, c8), Khg + (size_t)(j * 64 + r) * HD + c8);
        }
        CP_COMMIT();
    };

    // Prologue: G0 = {Qh, K0}; G1 = {K1}
    #pragma unroll
    for (int i = 0; i < 2; ++i) {
        int lin = tid + i * 256;
        int r = lin >> 3, c8 = (lin & 7) << 3;
        CP16(qh_b + swz16(r, c8), Qhg + (size_t)(q0 + r) * HD + c8);
    }
    #pragma unroll
    for (int i = 0; i < 2; ++i) {
        int lin = tid + i * 256;
        int r = lin >> 3, c8 = (lin & 7) << 3;
        CP16(kb_base + swz16(r, c8), Khg + (size_t)r * HD + c8);
    }
    CP_COMMIT();
    if (qt >= 1) issue_k(1, 1);

    float o[8][4];                 // partial O over this warp's key half
    #pragma unroll
    for (int j = 0; j < 8; ++j)
        #pragma unroll
        for (int q = 0; q < 4; ++q) o[j][q] = 0.f;
    float l0 = 0.f, l1 = 0.f;      // partial row sums over this key half

    unsigned qfh[4][4];

    for (int jt = 0; jt <= qt; ++jt) {
        if (jt < qt) { CP_WAIT1(); } else { CP_WAIT0(); }
        __syncthreads();
        if (jt + 2 <= qt) issue_k(jt + 2, (jt + 2) % 3);

        if (jt == 0) {   // hoist Q fragments once (rows wg*16..+15)
            #pragma unroll
            for (int t = 0; t < 4; ++t)
                LDSM_X4(qfh[t][0],qfh[t][1],qfh[t][2],qfh[t][3],
                        a_addr(qh_b, wg * 16, t, lane));
        }

        unsigned kh_b = kb_base + (unsigned)(jt % 3) * 8192u;

        // ---- S = Qh Kh^T for this warp's 32 keys (log2-domain) ----
        float s[4][4];
        #pragma unroll
        for (int j = 0; j < 4; ++j)
            #pragma unroll
            for (int q = 0; q < 4; ++q) s[j][q] = 0.f;

        #pragma unroll
        for (int t = 0; t < 4; ++t) {
            #pragma unroll
            for (int p = 0; p < 2; ++p) {
                unsigned h0,h1,h2,h3;
                LDSM_X4(h0,h1,h2,h3, b_addr(kh_b, kh * 32 + 16 * p, t, lane));
                MMA_F16(s[2*p],   qfh[t][0],qfh[t][1],qfh[t][2],qfh[t][3], h0,h1);
                MMA_F16(s[2*p+1], qfh[t][0],qfh[t][1],qfh[t][2],qfh[t][3], h2,h3);
            }
        }

        if (jt == qt) {   // causal mask on diagonal tile
            const int r0g = wg * 16 + g;
            #pragma unroll
            for (int j = 0; j < 4; ++j) {
                int c = kh * 32 + 8 * j + t4 * 2;
                if (c     > r0g)     s[j][0] = -1e30f;
                if (c + 1 > r0g)     s[j][1] = -1e30f;
                if (c     > r0g + 8) s[j][2] = -1e30f;
                if (c + 1 > r0g + 8) s[j][3] = -1e30f;
            }
        }

        // ---- Fixed-shift exp: p = exp2(s - 4); accumulate partial sums ----
        #pragma unroll
        for (int j = 0; j < 4; ++j) {
            s[j][0] = exp2f(s[j][0] - 4.f);
            s[j][1] = exp2f(s[j][1] - 4.f);
            s[j][2] = exp2f(s[j][2] - 4.f);
            s[j][3] = exp2f(s[j][3] - 4.f);
            l0 += s[j][0] + s[j][1];
            l1 += s[j][2] + s[j][3];
        }

        // ---- O += Ph · Vh over this key half (V == K, trans ldmatrix) ----
        #pragma unroll
        for (int t = 0; t < 2; ++t) {
            unsigned ph[4];
            ph[0] = packh2(s[2*t][0],   s[2*t][1]);
            ph[1] = packh2(s[2*t][2],   s[2*t][3]);
            ph[2] = packh2(s[2*t+1][0], s[2*t+1][1]);
            ph[3] = packh2(s[2*t+1][2], s[2*t+1][3]);
            #pragma unroll
            for (int p = 0; p < 4; ++p) {
                unsigned h0,h1,h2,h3;
                LDSM_X4_T(h0,h1,h2,h3, bt_addr(kh_b, 2 * kh + t, p, lane));
                MMA_F16(o[2*p],   ph[0],ph[1],ph[2],ph[3], h0,h1);
                MMA_F16(o[2*p+1], ph[0],ph[1],ph[2],ph[3], h2,h3);
            }
        }
    }

    // ---- Epilogue: reduce l over quad, then combine key halves via smem ----
    l0 += __shfl_xor_sync(0xffffffffu, l0, 1);
    l0 += __shfl_xor_sync(0xffffffffu, l0, 2);
    l1 += __shfl_xor_sync(0xffffffffu, l1, 1);
    l1 += __shfl_xor_sync(0xffffffffu, l1, 2);

    float* red  = (float*)sm;            // 64 x 68 f32 = 17408B
    float* lred = (float*)(sm + 17408);  // 64 f32
    __syncthreads();                     // all warps done reading K smem

    const int r0 = wg * 16 + g;
    if (kh == 1) {
        #pragma unroll
        for (int j = 0; j < 8; ++j) {
            int c = 8 * j + t4 * 2;
            *(float2*)&red[r0 * 68 + c]       = make_float2(o[j][0], o[j][1]);
            *(float2*)&red[(r0 + 8) * 68 + c] = make_float2(o[j][2], o[j][3]);
        }
        if (t4 == 0) { lred[r0] = l0; lred[r0 + 8] = l1; }
    }
    __syncthreads();
    if (kh == 0) {
        float il0 = 1.f / (l0 + lred[r0]);
        float il1 = 1.f / (l1 + lred[r0 + 8]);
        const int row0 = q0 + r0;
        #pragma unroll
        for (int j = 0; j < 8; ++j) {
            int c = 8 * j + t4 * 2;
            float2 a = *(float2*)&red[r0 * 68 + c];
            float2 d = *(float2*)&red[(r0 + 8) * 68 + c];
            float* d0 = out + ((size_t)b * SEQ + row0) * HD + c;
            *(float2*)d0 = make_float2((o[j][0] + a.x) * il0, (o[j][1] + a.y) * il0);
            *(float2*)(d0 + 8 * HD) =
                make_float2((o[j][2] + d.x) * il1, (o[j][3] + d.y) * il1);
        }
    }
}

// ---------------------------------------------------------------------------
extern "C" void kernel_launch(void* const* d_in, const int* in_sizes, int n_in,
                              void* d_out, int out_size) {
    const float* x  = (const float*)d_in[0];
    const float* Wq = (const float*)d_in[1];
    const float* Wk = (const float*)d_in[2];
    // d_in[3] (Wv) is an unused parameter in the reference model.

    __half *xh, *wh;
    cudaGetSymbolAddress((void**)&xh, g_Xh);
    cudaGetSymbolAddress((void**)&wh, g_Wh);

    round_kernel<<<MTOT * EMBED / 4 / 256, 256>>>(x, xh, MTOT * EMBED / 4);
    round_kernel<<<64, 256>>>(Wq, wh, HD * EMBED / 4);
    round_kernel<<<64, 256>>>(Wk, wh + 64 * EMBED, HD * EMBED / 4);

    const int proj_smem = 3 * 24576;            // 72KB, 3-stage
    cudaFuncSetAttribute(proj_kernel, cudaFuncAttributeMaxDynamicSharedMemorySize,
                         proj_smem);
    proj_kernel<<<2 * (MTOT / 128), 256, proj_smem>>>();

    const int attn_smem = 8192 + 3 * 8192;      // 32KB -> 2 CTAs/SM, 16 warps
    cudaFuncSetAttribute(attn_kernel, cudaFuncAttributeMaxDynamicSharedMemorySize,
                         attn_smem);
    attn_kernel<<<256, 256, attn_smem>>>((float*)d_out);
}

// round 14
// speedup vs baseline: 1.1212x; 1.0248x over previous
#include <cuda_runtime.h>
#include <cuda_fp16.h>

#define BATCH 4
#define SEQ   4096
#define EMBED 1024
#define HD    64
#define MTOT  (BATCH * SEQ)

// Prepared fp16 operands.
__device__ __half g_Xh[MTOT * EMBED];     // x rounded to fp16
__device__ __half g_Wh[128 * EMBED];      // [Wq;Wk] rounded to fp16
__device__ __half g_Qh[MTOT * HD];        // Q (pre-scaled by 0.125*log2e)
__device__ __half g_Kh[MTOT * HD];        // K row-major (V == K)

// ---------------------------------------------------------------------------
// PTX helpers
// ---------------------------------------------------------------------------
__device__ __forceinline__ unsigned su32(const void* p) {
    return (unsigned)__cvta_generic_to_shared(p);
}

#define LDSM_X4(r0,r1,r2,r3,addr) \
    asm volatile("ldmatrix.sync.aligned.m8n8.x4.shared.b16 {%0,%1,%2,%3}, [%4];" \
        : "=r"(r0),"=r"(r1),"=r"(r2),"=r"(r3) : "r"(addr))

#define LDSM_X4_T(r0,r1,r2,r3,addr) \
    asm volatile("ldmatrix.sync.aligned.m8n8.x4.trans.shared.b16 {%0,%1,%2,%3}, [%4];" \
        : "=r"(r0),"=r"(r1),"=r"(r2),"=r"(r3) : "r"(addr))

#define MMA_F16(d,a0,a1,a2,a3,b0,b1) \
    asm volatile("mma.sync.aligned.m16n8k16.row.col.f32.f16.f16.f32 " \
        "{%0,%1,%2,%3},{%4,%5,%6,%7},{%8,%9},{%0,%1,%2,%3};" \
        : "+f"((d)[0]),"+f"((d)[1]),"+f"((d)[2]),"+f"((d)[3]) \
        : "r"(a0),"r"(a1),"r"(a2),"r"(a3),"r"(b0),"r"(b1))

#define CP16(dst,src) asm volatile("cp.async.cg.shared.global [%0], [%1], 16;" :: "r"(dst),"l"(src))
#define CP_COMMIT()   asm volatile("cp.async.commit_group;")
#define CP_WAIT0()    asm volatile("cp.async.wait_group 0;")
#define CP_WAIT1()    asm volatile("cp.async.wait_group 1;")

// Byte offset inside an fp16 tile: 64 cols (128B rows), 16B-block xor swizzle.
__device__ __forceinline__ unsigned swz16(int r, int c8) {
    return (unsigned)(r * 128 + ((((c8 >> 3) ^ r) & 7) << 4) + ((c8 & 7) << 1));
}
// ldmatrix.x4 address: A fragment (m16 x k16) at (row_base, k-chunk t)
__device__ __forceinline__ unsigned a_addr(unsigned base, int row_base, int t, int lane) {
    int row = row_base + (lane & 15);
    int ch  = 2 * t + (lane >> 4);
    return base + row * 128 + (((ch ^ row) & 7) << 4);
}
// ldmatrix.x4 address: two B n8 tiles at n0, n0+8, k-chunk t (tile holds B^T rows=n).
__device__ __forceinline__ unsigned b_addr(unsigned base, int n0, int t, int lane) {
    int row = n0 + ((lane >> 4) << 3) + (lane & 7);
    int ch  = 2 * t + ((lane >> 3) & 1);
    return base + row * 128 + (((ch ^ row) & 7) << 4);
}
// trans B fragment for PV: rows = k (keys), cols = n (dims).
__device__ __forceinline__ unsigned bt_addr(unsigned base, int t, int p, int lane) {
    int row = 16 * t + (lane & 15);
    int c8  = 16 * p + ((lane >> 4) << 3);
    return base + swz16(row, c8);
}
__device__ __forceinline__ unsigned packh2(float a, float b) {
    __half2 h = __floats2half2_rn(a, b);
    return *(unsigned*)&h;
}

// ---------------------------------------------------------------------------
// f32 -> fp16 rounding pass. Memory-bound.
// ---------------------------------------------------------------------------
__global__ __launch_bounds__(256)
void round_kernel(const float* __restrict__ in, __half* __restrict__ h, int n4) {
    int i = blockIdx.x * blockDim.x + threadIdx.x;
    if (i >= n4) return;
    float4 v = ((const float4*)in)[i];
    ((uint2*)h)[i] = make_uint2(packh2(v.x, v.y), packh2(v.z, v.w));
}

// ---------------------------------------------------------------------------
// Projection: out[16384 x 128] = Xh @ Wh^T  (pure fp16 GEMM).
// Grid 256: (row-block 128) x (n-half 64). 256 threads, 8 warps x m16.
// ---------------------------------------------------------------------------
__global__ __launch_bounds__(256)
void proj_kernel() {
    extern __shared__ char sm[];
    const unsigned smb = su32(sm);

    const int tid = threadIdx.x, lane = tid & 31, w = tid >> 5;
    const int g = lane >> 2, t4 = lane & 3;
    const int row0 = (blockIdx.x >> 1) * 128;
    const int n0   = (blockIdx.x & 1) * 64;

    const unsigned STAGE = 24576u;   // Xh 16KB + Wh 8KB

    auto issue = [&](int kt, int st) {
        unsigned sb = smb + (unsigned)st * STAGE;
        #pragma unroll
        for (int i = 0; i < 6; ++i) {
            int lin = tid + i * 256;          // 0..1535
            if (lin < 1024) {
                int r = lin >> 3, c8 = (lin & 7) << 3;
                CP16(sb + swz16(r, c8),
                     g_Xh + (size_t)(row0 + r) * EMBED + kt * 64 + c8);
            } else {
                int q = lin - 1024; int r = q >> 3, c8 = (q & 7) << 3;
                CP16(sb + 16384u + swz16(r, c8),
                     g_Wh + (size_t)(n0 + r) * EMBED + kt * 64 + c8);
            }
        }
        CP_COMMIT();
    };

    float acc[8][4];
    #pragma unroll
    for (int j = 0; j < 8; ++j)
        #pragma unroll
        for (int q = 0; q < 4; ++q) acc[j][q] = 0.f;

    issue(0, 0);
    issue(1, 1);

    for (int kt = 0; kt < 16; ++kt) {
        if (kt < 15) { CP_WAIT1(); } else { CP_WAIT0(); }
        __syncthreads();
        if (kt + 2 < 16) issue(kt + 2, (kt + 2) % 3);

        unsigned sb = smb + (unsigned)(kt % 3) * STAGE;
        const unsigned xh_b = sb, wh_b = sb + 16384;

        #pragma unroll
        for (int t = 0; t < 4; ++t) {
            unsigned xa0,xa1,xa2,xa3;
            LDSM_X4(xa0,xa1,xa2,xa3, a_addr(xh_b, w * 16, t, lane));
            #pragma unroll
            for (int p = 0; p < 4; ++p) {
                unsigned h0,h1,h2,h3;
                LDSM_X4(h0,h1,h2,h3, b_addr(wh_b, 16 * p, t, lane));
                MMA_F16(acc[2*p],   xa0,xa1,xa2,xa3, h0,h1);
                MMA_F16(acc[2*p+1], xa0,xa1,xa2,xa3, h2,h3);
            }
        }
    }

    // Epilogue. n-half 0 -> Q (scaled by 0.125*log2e for exp2 softmax); 1 -> K.
    const float QS = 0.125f * 1.44269504f;
    const int r0g = row0 + w * 16 + g;
    if (n0 == 0) {
        #pragma unroll
        for (int j = 0; j < 8; ++j) {
            int n = 8 * j + t4 * 2;
            *(unsigned*)&g_Qh[(size_t)r0g * HD + n] =
                packh2(acc[j][0] * QS, acc[j][1] * QS);
            *(unsigned*)&g_Qh[(size_t)(r0g + 8) * HD + n] =
                packh2(acc[j][2] * QS, acc[j][3] * QS);
        }
    } else {
        #pragma unroll
        for (int j = 0; j < 8; ++j) {
            int n = 8 * j + t4 * 2;
            *(unsigned*)&g_Kh[(size_t)r0g * HD + n] = packh2(acc[j][0], acc[j][1]);
            *(unsigned*)&g_Kh[(size_t)(r0g + 8) * HD + n] = packh2(acc[j][2], acc[j][3]);
        }
    }
}

// ---------------------------------------------------------------------------
// Flash attention, fixed-shift softmax, KEY-SPLIT across 8 warps.
// SCHEDULE (inverted vs R13): single-CTA SMs (bids 108-147) get the LIGHTEST
// tiles (qt 0-9, <=10 iters); 2-CTA pair-SMs get the heavy tiles (qt 10-63)
// paired complementarily (~75 iters/SM at 16 warps). The per-iter barrier
// critical path on heavy tiles is now hidden by the co-resident CTA.
// ---------------------------------------------------------------------------
__global__ __launch_bounds__(256, 2)
void attn_kernel(float* __restrict__ out) {
    extern __shared__ char sm[];
    char* Qh = sm;                 // 8KB
    char* KB = sm + 8192;          // 3 x Kh x 8KB = 24KB

    const int tid = threadIdx.x, lane = tid & 31, w = tid >> 5;
    const int g = lane >> 2, t4 = lane & 3;
    const int wg = w & 3;          // row group
    const int kh = w >> 2;         // key half (0: keys 0-31, 1: keys 32-63)

    // bid and bid+148 share an SM (classic LUT = bid%148).
    int bid = blockIdx.x, qt, b;
    if (bid >= 108 && bid < 148) {
        int s5 = bid - 108; qt = s5 >> 2; b = s5 & 3;    // light tiles, 1-CTA SMs
    } else {
        int i = (bid < 108) ? bid : (363 - bid);         // 0..215
        qt = 10 + (i >> 2); b = i & 3;                   // heavy tiles, 2-CTA SMs
    }
    const int q0 = qt * 64;

    const __half* Qhg = g_Qh + (size_t)b * SEQ * HD;
    const __half* Khg = g_Kh + (size_t)b * SEQ * HD;

    const unsigned qh_b = su32(Qh);
    const unsigned kb_base = su32(KB);

    auto issue_k = [&](int j, int st) {
        unsigned kb = kb_base + (unsigned)st * 8192u;
        #pragma unroll
        for (int i = 0; i < 2; ++i) {
            int lin = tid + i * 256;          // 0..511
            int r = lin >> 3, c8 = (lin & 7) << 3;
            CP16(kb + swz16(r, c8), Khg + (size_t)(j * 64 + r) * HD + c8);
        }
        CP_COMMIT();
    };

    // Prologue: G0 = {Qh, K0}; G1 = {K1}
    #pragma unroll
    for (int i = 0; i < 2; ++i) {
        int lin = tid + i * 256;
        int r = lin >> 3, c8 = (lin & 7) << 3;
        CP16(qh_b + swz16(r, c8), Qhg + (size_t)(q0 + r) * HD + c8);
    }
    #pragma unroll
    for (int i = 0; i < 2; ++i) {
        int lin = tid + i * 256;
        int r = lin >> 3, c8 = (lin & 7) << 3;
        CP16(kb_base + swz16(r, c8), Khg + (size_t)r * HD + c8);
    }
    CP_COMMIT();
    if (qt >= 1) issue_k(1, 1);

    float o[8][4];                 // partial O over this warp's key half
    #pragma unroll
    for (int j = 0; j < 8; ++j)
        #pragma unroll
        for (int q = 0; q < 4; ++q) o[j][q] = 0.f;
    float l0 = 0.f, l1 = 0.f;      // partial row sums over this key half

    unsigned qfh[4][4];

    for (int jt = 0; jt <= qt; ++jt) {
        if (jt < qt) { CP_WAIT1(); } else { CP_WAIT0(); }
        __syncthreads();
        if (jt + 2 <= qt) issue_k(jt + 2, (jt + 2) % 3);

        if (jt == 0) {   // hoist Q fragments once (rows wg*16..+15)
            #pragma unroll
            for (int t = 0; t < 4; ++t)
                LDSM_X4(qfh[t][0],qfh[t][1],qfh[t][2],qfh[t][3],
                        a_addr(qh_b, wg * 16, t, lane));
        }

        unsigned kh_b = kb_base + (unsigned)(jt % 3) * 8192u;

        // ---- S = Qh Kh^T for this warp's 32 keys (log2-domain) ----
        float s[4][4];
        #pragma unroll
        for (int j = 0; j < 4; ++j)
            #pragma unroll
            for (int q = 0; q < 4; ++q) s[j][q] = 0.f;

        #pragma unroll
        for (int t = 0; t < 4; ++t) {
            #pragma unroll
            for (int p = 0; p < 2; ++p) {
                unsigned h0,h1,h2,h3;
                LDSM_X4(h0,h1,h2,h3, b_addr(kh_b, kh * 32 + 16 * p, t, lane));
                MMA_F16(s[2*p],   qfh[t][0],qfh[t][1],qfh[t][2],qfh[t][3], h0,h1);
                MMA_F16(s[2*p+1], qfh[t][0],qfh[t][1],qfh[t][2],qfh[t][3], h2,h3);
            }
        }

        if (jt == qt) {   // causal mask on diagonal tile
            const int r0g = wg * 16 + g;
            #pragma unroll
            for (int j = 0; j < 4; ++j) {
                int c = kh * 32 + 8 * j + t4 * 2;
                if (c     > r0g)     s[j][0] = -1e30f;
                if (c + 1 > r0g)     s[j][1] = -1e30f;
                if (c     > r0g + 8) s[j][2] = -1e30f;
                if (c + 1 > r0g + 8) s[j][3] = -1e30f;
            }
        }

        // ---- Fixed-shift exp: p = exp2(s - 4); accumulate partial sums ----
        #pragma unroll
        for (int j = 0; j < 4; ++j) {
            s[j][0] = exp2f(s[j][0] - 4.f);
            s[j][1] = exp2f(s[j][1] - 4.f);
            s[j][2] = exp2f(s[j][2] - 4.f);
            s[j][3] = exp2f(s[j][3] - 4.f);
            l0 += s[j][0] + s[j][1];
            l1 += s[j][2] + s[j][3];
        }

        // ---- O += Ph · Vh over this key half (V == K, trans ldmatrix) ----
        #pragma unroll
        for (int t = 0; t < 2; ++t) {
            unsigned ph[4];
            ph[0] = packh2(s[2*t][0],   s[2*t][1]);
            ph[1] = packh2(s[2*t][2],   s[2*t][3]);
            ph[2] = packh2(s[2*t+1][0], s[2*t+1][1]);
            ph[3] = packh2(s[2*t+1][2], s[2*t+1][3]);
            #pragma unroll
            for (int p = 0; p < 4; ++p) {
                unsigned h0,h1,h2,h3;
                LDSM_X4_T(h0,h1,h2,h3, bt_addr(kh_b, 2 * kh + t, p, lane));
                MMA_F16(o[2*p],   ph[0],ph[1],ph[2],ph[3], h0,h1);
                MMA_F16(o[2*p+1], ph[0],ph[1],ph[2],ph[3], h2,h3);
            }
        }
    }

    // ---- Epilogue: reduce l over quad, then combine key halves via smem ----
    l0 += __shfl_xor_sync(0xffffffffu, l0, 1);
    l0 += __shfl_xor_sync(0xffffffffu, l0, 2);
    l1 += __shfl_xor_sync(0xffffffffu, l1, 1);
    l1 += __shfl_xor_sync(0xffffffffu, l1, 2);

    float* red  = (float*)sm;            // 64 x 68 f32 = 17408B
    float* lred = (float*)(sm + 17408);  // 64 f32
    __syncthreads();                     // all warps done reading K smem

    const int r0 = wg * 16 + g;
    if (kh == 1) {
        #pragma unroll
        for (int j = 0; j < 8; ++j) {
            int c = 8 * j + t4 * 2;
            *(float2*)&red[r0 * 68 + c]       = make_float2(o[j][0], o[j][1]);
            *(float2*)&red[(r0 + 8) * 68 + c] = make_float2(o[j][2], o[j][3]);
        }
        if (t4 == 0) { lred[r0] = l0; lred[r0 + 8] = l1; }
    }
    __syncthreads();
    if (kh == 0) {
        float il0 = 1.f / (l0 + lred[r0]);
        float il1 = 1.f / (l1 + lred[r0 + 8]);
        const int row0 = q0 + r0;
        #pragma unroll
        for (int j = 0; j < 8; ++j) {
            int c = 8 * j + t4 * 2;
            float2 a = *(float2*)&red[r0 * 68 + c];
            float2 d = *(float2*)&red[(r0 + 8) * 68 + c];
            float* d0 = out + ((size_t)b * SEQ + row0) * HD + c;
            *(float2*)d0 = make_float2((o[j][0] + a.x) * il0, (o[j][1] + a.y) * il0);
            *(float2*)(d0 + 8 * HD) =
                make_float2((o[j][2] + d.x) * il1, (o[j][3] + d.y) * il1);
        }
    }
}

// ---------------------------------------------------------------------------
extern "C" void kernel_launch(void* const* d_in, const int* in_sizes, int n_in,
                              void* d_out, int out_size) {
    const float* x  = (const float*)d_in[0];
    const float* Wq = (const float*)d_in[1];
    const float* Wk = (const float*)d_in[2];
    // d_in[3] (Wv) is an unused parameter in the reference model.

    __half *xh, *wh;
    cudaGetSymbolAddress((void**)&xh, g_Xh);
    cudaGetSymbolAddress((void**)&wh, g_Wh);

    round_kernel<<<MTOT * EMBED / 4 / 256, 256>>>(x, xh, MTOT * EMBED / 4);
    round_kernel<<<64, 256>>>(Wq, wh, HD * EMBED / 4);
    round_kernel<<<64, 256>>>(Wk, wh + 64 * EMBED, HD * EMBED / 4);

    const int proj_smem = 3 * 24576;            // 72KB, 3-stage
    cudaFuncSetAttribute(proj_kernel, cudaFuncAttributeMaxDynamicSharedMemorySize,
                         proj_smem);
    proj_kernel<<<2 * (MTOT / 128), 256, proj_smem>>>();

    const int attn_smem = 8192 + 3 * 8192;      // 32KB -> 2 CTAs/SM, 16 warps
    cudaFuncSetAttribute(attn_kernel, cudaFuncAttributeMaxDynamicSharedMemorySize,
                         attn_smem);
    attn_kernel<<<256, 256, attn_smem>>>((float*)d_out);
}

// round 15
// speedup vs baseline: 1.1361x; 1.0133x over previous
#include <cuda_runtime.h>
#include <cuda_fp16.h>

#define BATCH 4
#define SEQ   4096
#define EMBED 1024
#define HD    64
#define MTOT  (BATCH * SEQ)

// Prepared fp16 operands.
__device__ __half g_Xh[MTOT * EMBED];     // x rounded to fp16
__device__ __half g_Wh[128 * EMBED];      // [Wq;Wk] rounded to fp16
__device__ __half g_Qh[MTOT * HD];        // Q (pre-scaled by 0.125*log2e)
__device__ __half g_Kh[MTOT * HD];        // K row-major (V == K)

// ---------------------------------------------------------------------------
// PTX helpers
// ---------------------------------------------------------------------------
__device__ __forceinline__ unsigned su32(const void* p) {
    return (unsigned)__cvta_generic_to_shared(p);
}

#define LDSM_X4(r0,r1,r2,r3,addr) \
    asm volatile("ldmatrix.sync.aligned.m8n8.x4.shared.b16 {%0,%1,%2,%3}, [%4];" \
        : "=r"(r0),"=r"(r1),"=r"(r2),"=r"(r3) : "r"(addr))

#define LDSM_X4_T(r0,r1,r2,r3,addr) \
    asm volatile("ldmatrix.sync.aligned.m8n8.x4.trans.shared.b16 {%0,%1,%2,%3}, [%4];" \
        : "=r"(r0),"=r"(r1),"=r"(r2),"=r"(r3) : "r"(addr))

#define MMA_F16(d,a0,a1,a2,a3,b0,b1) \
    asm volatile("mma.sync.aligned.m16n8k16.row.col.f32.f16.f16.f32 " \
        "{%0,%1,%2,%3},{%4,%5,%6,%7},{%8,%9},{%0,%1,%2,%3};" \
        : "+f"((d)[0]),"+f"((d)[1]),"+f"((d)[2]),"+f"((d)[3]) \
        : "r"(a0),"r"(a1),"r"(a2),"r"(a3),"r"(b0),"r"(b1))

#define CP16(dst,src) asm volatile("cp.async.cg.shared.global [%0], [%1], 16;" :: "r"(dst),"l"(src))
#define CP_COMMIT()   asm volatile("cp.async.commit_group;")
#define CP_WAIT0()    asm volatile("cp.async.wait_group 0;")
#define CP_WAIT1()    asm volatile("cp.async.wait_group 1;")

// Byte offset inside an fp16 tile: 64 cols (128B rows), 16B-block xor swizzle.
__device__ __forceinline__ unsigned swz16(int r, int c8) {
    return (unsigned)(r * 128 + ((((c8 >> 3) ^ r) & 7) << 4) + ((c8 & 7) << 1));
}
// ldmatrix.x4 address: A fragment (m16 x k16) at (row_base, k-chunk t)
__device__ __forceinline__ unsigned a_addr(unsigned base, int row_base, int t, int lane) {
    int row = row_base + (lane & 15);
    int ch  = 2 * t + (lane >> 4);
    return base + row * 128 + (((ch ^ row) & 7) << 4);
}
// ldmatrix.x4 address: two B n8 tiles at n0, n0+8, k-chunk t (tile holds B^T rows=n).
__device__ __forceinline__ unsigned b_addr(unsigned base, int n0, int t, int lane) {
    int row = n0 + ((lane >> 4) << 3) + (lane & 7);
    int ch  = 2 * t + ((lane >> 3) & 1);
    return base + row * 128 + (((ch ^ row) & 7) << 4);
}
// trans B fragment for PV: rows = k (keys), cols = n (dims).
__device__ __forceinline__ unsigned bt_addr(unsigned base, int t, int p, int lane) {
    int row = 16 * t + (lane & 15);
    int c8  = 16 * p + ((lane >> 4) << 3);
    return base + swz16(row, c8);
}
__device__ __forceinline__ unsigned packh2(float a, float b) {
    __half2 h = __floats2half2_rn(a, b);
    return *(unsigned*)&h;
}

// ---------------------------------------------------------------------------
// f32 -> fp16 rounding pass. Memory-bound.
// ---------------------------------------------------------------------------
__global__ __launch_bounds__(256)
void round_kernel(const float* __restrict__ in, __half* __restrict__ h, int n4) {
    int i = blockIdx.x * blockDim.x + threadIdx.x;
    if (i >= n4) return;
    float4 v = ((const float4*)in)[i];
    ((uint2*)h)[i] = make_uint2(packh2(v.x, v.y), packh2(v.z, v.w));
}

// ---------------------------------------------------------------------------
// Projection: out[16384 x 128] = Xh @ Wh^T  (pure fp16 GEMM).
// Grid 256: (row-block 128) x (n-half 64). 256 threads, 8 warps x m16.
// ---------------------------------------------------------------------------
__global__ __launch_bounds__(256)
void proj_kernel() {
    extern __shared__ char sm[];
    const unsigned smb = su32(sm);

    const int tid = threadIdx.x, lane = tid & 31, w = tid >> 5;
    const int g = lane >> 2, t4 = lane & 3;
    const int row0 = (blockIdx.x >> 1) * 128;
    const int n0   = (blockIdx.x & 1) * 64;

    const unsigned STAGE = 24576u;   // Xh 16KB + Wh 8KB

    auto issue = [&](int kt, int st) {
        unsigned sb = smb + (unsigned)st * STAGE;
        #pragma unroll
        for (int i = 0; i < 6; ++i) {
            int lin = tid + i * 256;          // 0..1535
            if (lin < 1024) {
                int r = lin >> 3, c8 = (lin & 7) << 3;
                CP16(sb + swz16(r, c8),
                     g_Xh + (size_t)(row0 + r) * EMBED + kt * 64 + c8);
            } else {
                int q = lin - 1024; int r = q >> 3, c8 = (q & 7) << 3;
                CP16(sb + 16384u + swz16(r, c8),
                     g_Wh + (size_t)(n0 + r) * EMBED + kt * 64 + c8);
            }
        }
        CP_COMMIT();
    };

    float acc[8][4];
    #pragma unroll
    for (int j = 0; j < 8; ++j)
        #pragma unroll
        for (int q = 0; q < 4; ++q) acc[j][q] = 0.f;

    issue(0, 0);
    issue(1, 1);

    for (int kt = 0; kt < 16; ++kt) {
        if (kt < 15) { CP_WAIT1(); } else { CP_WAIT0(); }
        __syncthreads();
        if (kt + 2 < 16) issue(kt + 2, (kt + 2) % 3);

        unsigned sb = smb + (unsigned)(kt % 3) * STAGE;
        const unsigned xh_b = sb, wh_b = sb + 16384;

        #pragma unroll
        for (int t = 0; t < 4; ++t) {
            unsigned xa0,xa1,xa2,xa3;
            LDSM_X4(xa0,xa1,xa2,xa3, a_addr(xh_b, w * 16, t, lane));
            #pragma unroll
            for (int p = 0; p < 4; ++p) {
                unsigned h0,h1,h2,h3;
                LDSM_X4(h0,h1,h2,h3, b_addr(wh_b, 16 * p, t, lane));
                MMA_F16(acc[2*p],   xa0,xa1,xa2,xa3, h0,h1);
                MMA_F16(acc[2*p+1], xa0,xa1,xa2,xa3, h2,h3);
            }
        }
    }

    // Epilogue. n-half 0 -> Q (scaled by 0.125*log2e for exp2 softmax); 1 -> K.
    const float QS = 0.125f * 1.44269504f;
    const int r0g = row0 + w * 16 + g;
    if (n0 == 0) {
        #pragma unroll
        for (int j = 0; j < 8; ++j) {
            int n = 8 * j + t4 * 2;
            *(unsigned*)&g_Qh[(size_t)r0g * HD + n] =
                packh2(acc[j][0] * QS, acc[j][1] * QS);
            *(unsigned*)&g_Qh[(size_t)(r0g + 8) * HD + n] =
                packh2(acc[j][2] * QS, acc[j][3] * QS);
        }
    } else {
        #pragma unroll
        for (int j = 0; j < 8; ++j) {
            int n = 8 * j + t4 * 2;
            *(unsigned*)&g_Kh[(size_t)r0g * HD + n] = packh2(acc[j][0], acc[j][1]);
            *(unsigned*)&g_Kh[(size_t)(r0g + 8) * HD + n] = packh2(acc[j][2], acc[j][3]);
        }
    }
}

// ---------------------------------------------------------------------------
// Flash attention, fixed-shift softmax, KEY-SPLIT across 8 warps.
// SCHEDULE (finish-time balanced, c_single~1400 cyc/iter, c_pair~1140):
//   singles (bids 108-147, 1 CTA/SM): qt 44..53   (<=54 iters x 1400 ~ 75.6k)
//   pairs   (bid <-> bid+148, 2 CTA/SM):
//     bids 0..39    <-> 148..187 : qt 54+i <-> 9-i   (sum 65 iters x 1140 ~ 74.1k)
//     bids 40..107  <-> 188..255 : qt 10+i <-> 43-i  (sum 55 iters, early finish)
// ---------------------------------------------------------------------------
__global__ __launch_bounds__(256, 2)
void attn_kernel(float* __restrict__ out) {
    extern __shared__ char sm[];
    char* Qh = sm;                 // 8KB
    char* KB = sm + 8192;          // 3 x Kh x 8KB = 24KB

    const int tid = threadIdx.x, lane = tid & 31, w = tid >> 5;
    const int g = lane >> 2, t4 = lane & 3;
    const int wg = w & 3;          // row group
    const int kh = w >> 2;         // key half (0: keys 0-31, 1: keys 32-63)

    // bid and bid+148 share an SM (classic LUT = bid%148).
    const int bid = blockIdx.x;
    const int b = bid & 3;         // all segment bases are multiples of 4
    int qt;
    if (bid >= 108 && bid < 148)  qt = 44 + ((bid - 108) >> 2);  // singles
    else if (bid < 40)            qt = 54 + (bid >> 2);          // heavy of 65-pairs
    else if (bid < 108)           qt = 10 + ((bid - 40) >> 2);   // 10..26
    else if (bid < 188)           qt = 9  - ((bid - 148) >> 2);  // 0..9 (partners)
    else                          qt = 43 - ((bid - 188) >> 2);  // 27..43 (partners)
    const int q0 = qt * 64;

    const __half* Qhg = g_Qh + (size_t)b * SEQ * HD;
    const __half* Khg = g_Kh + (size_t)b * SEQ * HD;

    const unsigned qh_b = su32(Qh);
    const unsigned kb_base = su32(KB);

    auto issue_k = [&](int j, int st) {
        unsigned kb = kb_base + (unsigned)st * 8192u;
        #pragma unroll
        for (int i = 0; i < 2; ++i) {
            int lin = tid + i * 256;          // 0..511
            int r = lin >> 3, c8 = (lin & 7) << 3;
            CP16(kb + swz16(r, c8), Khg + (size_t)(j * 64 + r) * HD + c8);
        }
        CP_COMMIT();
    };

    // Prologue: G0 = {Qh, K0}; G1 = {K1}
    #pragma unroll
    for (int i = 0; i < 2; ++i) {
        int lin = tid + i * 256;
        int r = lin >> 3, c8 = (lin & 7) << 3;
        CP16(qh_b + swz16(r, c8), Qhg + (size_t)(q0 + r) * HD + c8);
    }
    #pragma unroll
    for (int i = 0; i < 2; ++i) {
        int lin = tid + i * 256;
        int r = lin >> 3, c8 = (lin & 7) << 3;
        CP16(kb_base + swz16(r, c8), Khg + (size_t)r * HD + c8);
    }
    CP_COMMIT();
    if (qt >= 1) issue_k(1, 1);

    float o[8][4];                 // partial O over this warp's key half
    #pragma unroll
    for (int j = 0; j < 8; ++j)
        #pragma unroll
        for (int q = 0; q < 4; ++q) o[j][q] = 0.f;
    float l0 = 0.f, l1 = 0.f;      // partial row sums over this key half

    unsigned qfh[4][4];

    for (int jt = 0; jt <= qt; ++jt) {
        if (jt < qt) { CP_WAIT1(); } else { CP_WAIT0(); }
        __syncthreads();
        if (jt + 2 <= qt) issue_k(jt + 2, (jt + 2) % 3);

        if (jt == 0) {   // hoist Q fragments once (rows wg*16..+15)
            #pragma unroll
            for (int t = 0; t < 4; ++t)
                LDSM_X4(qfh[t][0],qfh[t][1],qfh[t][2],qfh[t][3],
                        a_addr(qh_b, wg * 16, t, lane));
        }

        unsigned kh_b = kb_base + (unsigned)(jt % 3) * 8192u;

        // ---- S = Qh Kh^T for this warp's 32 keys (log2-domain) ----
        float s[4][4];
        #pragma unroll
        for (int j = 0; j < 4; ++j)
            #pragma unroll
            for (int q = 0; q < 4; ++q) s[j][q] = 0.f;

        #pragma unroll
        for (int t = 0; t < 4; ++t) {
            #pragma unroll
            for (int p = 0; p < 2; ++p) {
                unsigned h0,h1,h2,h3;
                LDSM_X4(h0,h1,h2,h3, b_addr(kh_b, kh * 32 + 16 * p, t, lane));
                MMA_F16(s[2*p],   qfh[t][0],qfh[t][1],qfh[t][2],qfh[t][3], h0,h1);
                MMA_F16(s[2*p+1], qfh[t][0],qfh[t][1],qfh[t][2],qfh[t][3], h2,h3);
            }
        }

        if (jt == qt) {   // causal mask on diagonal tile
            const int r0g = wg * 16 + g;
            #pragma unroll
            for (int j = 0; j < 4; ++j) {
                int c = kh * 32 + 8 * j + t4 * 2;
                if (c     > r0g)     s[j][0] = -1e30f;
                if (c + 1 > r0g)     s[j][1] = -1e30f;
                if (c     > r0g + 8) s[j][2] = -1e30f;
                if (c + 1 > r0g + 8) s[j][3] = -1e30f;
            }
        }

        // ---- Fixed-shift exp: p = exp2(s - 4); accumulate partial sums ----
        #pragma unroll
        for (int j = 0; j < 4; ++j) {
            s[j][0] = exp2f(s[j][0] - 4.f);
            s[j][1] = exp2f(s[j][1] - 4.f);
            s[j][2] = exp2f(s[j][2] - 4.f);
            s[j][3] = exp2f(s[j][3] - 4.f);
            l0 += s[j][0] + s[j][1];
            l1 += s[j][2] + s[j][3];
        }

        // ---- O += Ph · Vh over this key half (V == K, trans ldmatrix) ----
        #pragma unroll
        for (int t = 0; t < 2; ++t) {
            unsigned ph[4];
            ph[0] = packh2(s[2*t][0],   s[2*t][1]);
            ph[1] = packh2(s[2*t][2],   s[2*t][3]);
            ph[2] = packh2(s[2*t+1][0], s[2*t+1][1]);
            ph[3] = packh2(s[2*t+1][2], s[2*t+1][3]);
            #pragma unroll
            for (int p = 0; p < 4; ++p) {
                unsigned h0,h1,h2,h3;
                LDSM_X4_T(h0,h1,h2,h3, bt_addr(kh_b, 2 * kh + t, p, lane));
                MMA_F16(o[2*p],   ph[0],ph[1],ph[2],ph[3], h0,h1);
                MMA_F16(o[2*p+1], ph[0],ph[1],ph[2],ph[3], h2,h3);
            }
        }
    }

    // ---- Epilogue: reduce l over quad, then combine key halves via smem ----
    l0 += __shfl_xor_sync(0xffffffffu, l0, 1);
    l0 += __shfl_xor_sync(0xffffffffu, l0, 2);
    l1 += __shfl_xor_sync(0xffffffffu, l1, 1);
    l1 += __shfl_xor_sync(0xffffffffu, l1, 2);

    float* red  = (float*)sm;            // 64 x 68 f32 = 17408B
    float* lred = (float*)(sm + 17408);  // 64 f32
    __syncthreads();                     // all warps done reading K smem

    const int r0 = wg * 16 + g;
    if (kh == 1) {
        #pragma unroll
        for (int j = 0; j < 8; ++j) {
            int c = 8 * j + t4 * 2;
            *(float2*)&red[r0 * 68 + c]       = make_float2(o[j][0], o[j][1]);
            *(float2*)&red[(r0 + 8) * 68 + c] = make_float2(o[j][2], o[j][3]);
        }
        if (t4 == 0) { lred[r0] = l0; lred[r0 + 8] = l1; }
    }
    __syncthreads();
    if (kh == 0) {
        float il0 = 1.f / (l0 + lred[r0]);
        float il1 = 1.f / (l1 + lred[r0 + 8]);
        const int row0 = q0 + r0;
        #pragma unroll
        for (int j = 0; j < 8; ++j) {
            int c = 8 * j + t4 * 2;
            float2 a = *(float2*)&red[r0 * 68 + c];
            float2 d = *(float2*)&red[(r0 + 8) * 68 + c];
            float* d0 = out + ((size_t)b * SEQ + row0) * HD + c;
            *(float2*)d0 = make_float2((o[j][0] + a.x) * il0, (o[j][1] + a.y) * il0);
            *(float2*)(d0 + 8 * HD) =
                make_float2((o[j][2] + d.x) * il1, (o[j][3] + d.y) * il1);
        }
    }
}

// ---------------------------------------------------------------------------
extern "C" void kernel_launch(void* const* d_in, const int* in_sizes, int n_in,
                              void* d_out, int out_size) {
    const float* x  = (const float*)d_in[0];
    const float* Wq = (const float*)d_in[1];
    const float* Wk = (const float*)d_in[2];
    // d_in[3] (Wv) is an unused parameter in the reference model.

    __half *xh, *wh;
    cudaGetSymbolAddress((void**)&xh, g_Xh);
    cudaGetSymbolAddress((void**)&wh, g_Wh);

    round_kernel<<<MTOT * EMBED / 4 / 256, 256>>>(x, xh, MTOT * EMBED / 4);
    round_kernel<<<64, 256>>>(Wq, wh, HD * EMBED / 4);
    round_kernel<<<64, 256>>>(Wk, wh + 64 * EMBED, HD * EMBED / 4);

    const int proj_smem = 3 * 24576;            // 72KB, 3-stage
    cudaFuncSetAttribute(proj_kernel, cudaFuncAttributeMaxDynamicSharedMemorySize,
                         proj_smem);
    proj_kernel<<<2 * (MTOT / 128), 256, proj_smem>>>();

    const int attn_smem = 8192 + 3 * 8192;      // 32KB -> 2 CTAs/SM, 16 warps
    cudaFuncSetAttribute(attn_kernel, cudaFuncAttributeMaxDynamicSharedMemorySize,
                         attn_smem);
    attn_kernel<<<256, 256, attn_smem>>>((float*)d_out);
}

// round 16
// speedup vs baseline: 1.3164x; 1.1586x over previous
#include <cuda_runtime.h>
#include <cuda_fp16.h>

#define BATCH 4
#define SEQ   4096
#define EMBED 1024
#define HD    64
#define MTOT  (BATCH * SEQ)

// Prepared fp16 operands.
__device__ __half g_Wh[128 * EMBED];      // [Wq;Wk] rounded to fp16
__device__ __half g_Qh[MTOT * HD];        // Q (pre-scaled by 0.125*log2e)
__device__ __half g_Kh[MTOT * HD];        // K row-major (V == K)

// ---------------------------------------------------------------------------
// PTX helpers
// ---------------------------------------------------------------------------
__device__ __forceinline__ unsigned su32(const void* p) {
    return (unsigned)__cvta_generic_to_shared(p);
}

#define LDSM_X4(r0,r1,r2,r3,addr) \
    asm volatile("ldmatrix.sync.aligned.m8n8.x4.shared.b16 {%0,%1,%2,%3}, [%4];" \
        : "=r"(r0),"=r"(r1),"=r"(r2),"=r"(r3) : "r"(addr))

#define LDSM_X4_T(r0,r1,r2,r3,addr) \
    asm volatile("ldmatrix.sync.aligned.m8n8.x4.trans.shared.b16 {%0,%1,%2,%3}, [%4];" \
        : "=r"(r0),"=r"(r1),"=r"(r2),"=r"(r3) : "r"(addr))

#define MMA_F16(d,a0,a1,a2,a3,b0,b1) \
    asm volatile("mma.sync.aligned.m16n8k16.row.col.f32.f16.f16.f32 " \
        "{%0,%1,%2,%3},{%4,%5,%6,%7},{%8,%9},{%0,%1,%2,%3};" \
        : "+f"((d)[0]),"+f"((d)[1]),"+f"((d)[2]),"+f"((d)[3]) \
        : "r"(a0),"r"(a1),"r"(a2),"r"(a3),"r"(b0),"r"(b1))

#define CP16(dst,src) asm volatile("cp.async.cg.shared.global [%0], [%1], 16;" :: "r"(dst),"l"(src))
#define CP_COMMIT()   asm volatile("cp.async.commit_group;")
#define CP_WAIT0()    asm volatile("cp.async.wait_group 0;")
#define CP_WAIT1()    asm volatile("cp.async.wait_group 1;")

// Byte offset inside an fp16 tile: 64 cols (128B rows), 16B-block xor swizzle.
__device__ __forceinline__ unsigned swz16(int r, int c8) {
    return (unsigned)(r * 128 + ((((c8 >> 3) ^ r) & 7) << 4) + ((c8 & 7) << 1));
}
// ldmatrix.x4 address: A fragment (m16 x k16) at (row_base, k-chunk t)
__device__ __forceinline__ unsigned a_addr(unsigned base, int row_base, int t, int lane) {
    int row = row_base + (lane & 15);
    int ch  = 2 * t + (lane >> 4);
    return base + row * 128 + (((ch ^ row) & 7) << 4);
}
// ldmatrix.x4 address: two B n8 tiles at n0, n0+8, k-chunk t (tile holds B^T rows=n).
__device__ __forceinline__ unsigned b_addr(unsigned base, int n0, int t, int lane) {
    int row = n0 + ((lane >> 4) << 3) + (lane & 7);
    int ch  = 2 * t + ((lane >> 3) & 1);
    return base + row * 128 + (((ch ^ row) & 7) << 4);
}
// trans B fragment for PV: rows = k (keys), cols = n (dims). gt = global k16 chunk.
__device__ __forceinline__ unsigned bt_addr(unsigned base, int gt, int p, int lane) {
    int row = 16 * gt + (lane & 15);
    int c8  = 16 * p + ((lane >> 4) << 3);
    return base + swz16(row, c8);
}
__device__ __forceinline__ unsigned packh2(float a, float b) {
    __half2 h = __floats2half2_rn(a, b);
    return *(unsigned*)&h;
}

// ---------------------------------------------------------------------------
// f32 -> fp16 rounding pass (W only; x conversion is fused into proj).
// ---------------------------------------------------------------------------
__global__ __launch_bounds__(256)
void round_kernel(const float* __restrict__ in, __half* __restrict__ h, int n4) {
    int i = blockIdx.x * blockDim.x + threadIdx.x;
    if (i >= n4) return;
    float4 v = ((const float4*)in)[i];
    ((uint2*)h)[i] = make_uint2(packh2(v.x, v.y), packh2(v.z, v.w));
}

// ---------------------------------------------------------------------------
// FUSED projection: out[16384 x 128] = fp16(x) @ Wh^T.
// Reads x as f32 directly (cp.async k32 stages), converts f32->fp16 in smem
// one stage ahead of the mma (skewed, one barrier per stage).
// Buffers: Xf f32 3x16KB, Xh fp16 2x16KB, W fp16 2x8KB (4 logical k32 stages).
// Grid 256: (row-block 128) x (n-half 64). 256 threads, 8 warps x m16.
// ---------------------------------------------------------------------------
__global__ __launch_bounds__(256, 2)
void proj_kernel(const float* __restrict__ x) {
    extern __shared__ char sm[];
    const unsigned smb = su32(sm);
    const unsigned XF = 0u, XH = 49152u, WB = 81920u;

    const int tid = threadIdx.x, lane = tid & 31, w = tid >> 5;
    const int g = lane >> 2, t4 = lane & 3;
    const int row0 = (blockIdx.x >> 1) * 128;
    const int n0   = (blockIdx.x & 1) * 64;

    // Stage kt (k-cols kt*32..+31): cp x f32 (16KB, chunk-swizzled) + W fp16 (4KB).
    auto issue = [&](int kt) {
        unsigned xfb = smb + XF + (unsigned)(kt % 3) * 16384u;
        #pragma unroll
        for (int i = 0; i < 4; ++i) {
            int lin = tid + i * 256;             // 0..1023 16B chunks
            int r = lin >> 3, ch = lin & 7;
            CP16(xfb + (unsigned)(r * 128 + (((ch ^ (r & 7)) & 7) << 4)),
                 x + (size_t)(row0 + r) * EMBED + kt * 32 + ch * 4);
        }
        {
            int r = tid >> 2, c8 = (tid & 3) << 3;
            unsigned wb = smb + WB + (unsigned)((kt & 3) >> 1) * 8192u;
            CP16(wb + swz16(r, ((kt & 1) << 5) + c8),
                 g_Wh + (size_t)(n0 + r) * EMBED + kt * 32 + c8);
        }
        CP_COMMIT();
    };

    // Convert staged f32 (stage kt) -> fp16 tile Xh[kt&1]. 256 thr x 16 elems.
    auto convert = [&](int kt) {
        char* xf = sm + XF + (size_t)(kt % 3) * 16384;
        char* xh = sm + XH + (size_t)(kt & 1) * 16384;
        int r = tid >> 1, cb = (tid & 1) * 4;    // 4 f32 16B-chunks = 16 cols
        #pragma unroll
        for (int jj = 0; jj < 2; ++jj) {
            int ch0 = cb + 2 * jj, ch1 = ch0 + 1;
            float4 f0 = *(const float4*)(xf + r * 128 + (((ch0 ^ (r & 7)) & 7) << 4));
            float4 f1 = *(const float4*)(xf + r * 128 + (((ch1 ^ (r & 7)) & 7) << 4));
            uint4 u;
            u.x = packh2(f0.x, f0.y); u.y = packh2(f0.z, f0.w);
            u.z = packh2(f1.x, f1.y); u.w = packh2(f1.z, f1.w);
            *(uint4*)(xh + swz16(r, (tid & 1) * 16 + 8 * jj)) = u;
        }
    };

    float acc[8][4];
    #pragma unroll
    for (int j = 0; j < 8; ++j)
        #pragma unroll
        for (int q = 0; q < 4; ++q) acc[j][q] = 0.f;

    // Prologue
    issue(0);
    issue(1);
    CP_WAIT1();
    __syncthreads();
    convert(0);

    for (int kt = 0; kt < 32; ++kt) {
        if (kt + 2 < 32) { issue(kt + 2); CP_WAIT1(); } else { CP_WAIT0(); }
        __syncthreads();
        if (kt + 1 < 32) convert(kt + 1);

        unsigned xhb = smb + XH + (unsigned)(kt & 1) * 16384u;
        unsigned wb  = smb + WB + (unsigned)((kt & 3) >> 1) * 8192u;
        const int half = kt & 1;

        #pragma unroll
        for (int t = 0; t < 2; ++t) {
            unsigned xa0,xa1,xa2,xa3;
            LDSM_X4(xa0,xa1,xa2,xa3, a_addr(xhb, w * 16, t, lane));
            #pragma unroll
            for (int p = 0; p < 4; ++p) {
                int row = 16 * p + ((lane >> 4) << 3) + (lane & 7);
                int ch  = 4 * half + 2 * t + ((lane >> 3) & 1);
                unsigned baddr = wb + row * 128 + (((ch ^ (row & 7)) & 7) << 4);
                unsigned h0,h1,h2,h3;
                LDSM_X4(h0,h1,h2,h3, baddr);
                MMA_F16(acc[2*p],   xa0,xa1,xa2,xa3, h0,h1);
                MMA_F16(acc[2*p+1], xa0,xa1,xa2,xa3, h2,h3);
            }
        }
    }

    // Epilogue. n-half 0 -> Q (scaled by 0.125*log2e for exp2 softmax); 1 -> K.
    const float QS = 0.125f * 1.44269504f;
    const int r0g = row0 + w * 16 + g;
    if (n0 == 0) {
        #pragma unroll
        for (int j = 0; j < 8; ++j) {
            int n = 8 * j + t4 * 2;
            *(unsigned*)&g_Qh[(size_t)r0g * HD + n] =
                packh2(acc[j][0] * QS, acc[j][1] * QS);
            *(unsigned*)&g_Qh[(size_t)(r0g + 8) * HD + n] =
                packh2(acc[j][2] * QS, acc[j][3] * QS);
        }
    } else {
        #pragma unroll
        for (int j = 0; j < 8; ++j) {
            int n = 8 * j + t4 * 2;
            *(unsigned*)&g_Kh[(size_t)r0g * HD + n] = packh2(acc[j][0], acc[j][1]);
            *(unsigned*)&g_Kh[(size_t)(r0g + 8) * HD + n] = packh2(acc[j][2], acc[j][3]);
        }
    }
}

// ---------------------------------------------------------------------------
// Flash attention, fixed-shift softmax, 128-KEY tiles, key-split 8 warps:
//   warp (w&3) = row group (m16), warp (w>>2) = key half (64 keys each).
// nit = (qt>>1)+1 iterations (half the barriers of 64-key tiles).
// Schedule: finish-time balanced (same mapping as R15; balance preserved).
// ---------------------------------------------------------------------------
__global__ __launch_bounds__(256, 2)
void attn_kernel(float* __restrict__ out) {
    extern __shared__ char sm[];
    char* Qh = sm;                 // 8KB
    char* KB = sm + 8192;          // 3 x 16KB K tiles (128 keys x 64 dims)

    const int tid = threadIdx.x, lane = tid & 31, w = tid >> 5;
    const int g = lane >> 2, t4 = lane & 3;
    const int wg = w & 3;          // row group
    const int kh = w >> 2;         // key half (0: keys 0-63, 1: keys 64-127)

    // bid and bid+148 share an SM (classic LUT = bid%148).
    const int bid = blockIdx.x;
    const int b = bid & 3;
    int qt;
    if (bid >= 108 && bid < 148)  qt = 44 + ((bid - 108) >> 2);
    else if (bid < 40)            qt = 54 + (bid >> 2);
    else if (bid < 108)           qt = 10 + ((bid - 40) >> 2);
    else if (bid < 188)           qt = 9  - ((bid - 148) >> 2);
    else                          qt = 43 - ((bid - 188) >> 2);
    const int q0 = qt * 64;
    const int nit = (qt >> 1) + 1;          // 128-key tiles covering keys <= q0+63

    const __half* Qhg = g_Qh + (size_t)b * SEQ * HD;
    const __half* Khg = g_Kh + (size_t)b * SEQ * HD;

    const unsigned qh_b = su32(Qh);
    const unsigned kb_base = su32(KB);

    auto issue_k = [&](int j, int st) {
        unsigned kb = kb_base + (unsigned)st * 16384u;
        #pragma unroll
        for (int i = 0; i < 4; ++i) {
            int lin = tid + i * 256;          // 0..1023
            int r = lin >> 3, c8 = (lin & 7) << 3;
            CP16(kb + swz16(r, c8), Khg + (size_t)(j * 128 + r) * HD + c8);
        }
        CP_COMMIT();
    };

    // Prologue: G0 = {Qh, K-tile 0}; G1 = {K-tile 1}
    #pragma unroll
    for (int i = 0; i < 2; ++i) {
        int lin = tid + i * 256;
        int r = lin >> 3, c8 = (lin & 7) << 3;
        CP16(qh_b + swz16(r, c8), Qhg + (size_t)(q0 + r) * HD + c8);
    }
    #pragma unroll
    for (int i = 0; i < 4; ++i) {
        int lin = tid + i * 256;
        int r = lin >> 3, c8 = (lin & 7) << 3;
        CP16(kb_base + swz16(r, c8), Khg + (size_t)r * HD + c8);
    }
    CP_COMMIT();
    if (nit >= 2) issue_k(1, 1);

    float o[8][4];                 // partial O over this warp's key half
    #pragma unroll
    for (int j = 0; j < 8; ++j)
        #pragma unroll
        for (int q = 0; q < 4; ++q) o[j][q] = 0.f;
    float l0 = 0.f, l1 = 0.f;

    unsigned qfh[4][4];

    for (int jt = 0; jt < nit; ++jt) {
        if (jt < nit - 1) { CP_WAIT1(); } else { CP_WAIT0(); }
        __syncthreads();
        if (jt + 2 < nit) issue_k(jt + 2, (jt + 2) % 3);

        if (jt == 0) {   // hoist Q fragments once (rows wg*16..+15)
            #pragma unroll
            for (int t = 0; t < 4; ++t)
                LDSM_X4(qfh[t][0],qfh[t][1],qfh[t][2],qfh[t][3],
                        a_addr(qh_b, wg * 16, t, lane));
        }

        unsigned kh_b = kb_base + (unsigned)(jt % 3) * 16384u;

        // ---- S = Qh Kh^T for this warp's 64 keys (log2-domain) ----
        float s[8][4];
        #pragma unroll
        for (int j = 0; j < 8; ++j)
            #pragma unroll
            for (int q = 0; q < 4; ++q) s[j][q] = 0.f;

        #pragma unroll
        for (int t = 0; t < 4; ++t) {
            #pragma unroll
            for (int p = 0; p < 4; ++p) {
                unsigned h0,h1,h2,h3;
                LDSM_X4(h0,h1,h2,h3, b_addr(kh_b, kh * 64 + 16 * p, t, lane));
                MMA_F16(s[2*p],   qfh[t][0],qfh[t][1],qfh[t][2],qfh[t][3], h0,h1);
                MMA_F16(s[2*p+1], qfh[t][0],qfh[t][1],qfh[t][2],qfh[t][3], h2,h3);
            }
        }

        if (jt == nit - 1) {   // causal mask on last tile
            const int r0g = wg * 16 + g;
            const int co = jt * 128 + kh * 64 - q0 + t4 * 2;
            #pragma unroll
            for (int j = 0; j < 8; ++j) {
                int c = co + 8 * j;
                if (c     > r0g)     s[j][0] = -1e30f;
                if (c + 1 > r0g)     s[j][1] = -1e30f;
                if (c     > r0g + 8) s[j][2] = -1e30f;
                if (c + 1 > r0g + 8) s[j][3] = -1e30f;
            }
        }

        // ---- Fixed-shift exp: p = exp2(s - 4); accumulate partial sums ----
        #pragma unroll
        for (int j = 0; j < 8; ++j) {
            s[j][0] = exp2f(s[j][0] - 4.f);
            s[j][1] = exp2f(s[j][1] - 4.f);
            s[j][2] = exp2f(s[j][2] - 4.f);
            s[j][3] = exp2f(s[j][3] - 4.f);
            l0 += s[j][0] + s[j][1];
            l1 += s[j][2] + s[j][3];
        }

        // ---- O += Ph · Vh over this key half (V == K, trans ldmatrix) ----
        #pragma unroll
        for (int t = 0; t < 4; ++t) {
            unsigned ph[4];
            ph[0] = packh2(s[2*t][0],   s[2*t][1]);
            ph[1] = packh2(s[2*t][2],   s[2*t][3]);
            ph[2] = packh2(s[2*t+1][0], s[2*t+1][1]);
            ph[3] = packh2(s[2*t+1][2], s[2*t+1][3]);
            #pragma unroll
            for (int p = 0; p < 4; ++p) {
                unsigned h0,h1,h2,h3;
                LDSM_X4_T(h0,h1,h2,h3, bt_addr(kh_b, kh * 4 + t, p, lane));
                MMA_F16(o[2*p],   ph[0],ph[1],ph[2],ph[3], h0,h1);
                MMA_F16(o[2*p+1], ph[0],ph[1],ph[2],ph[3], h2,h3);
            }
        }
    }

    // ---- Epilogue: reduce l over quad, then combine key halves via smem ----
    l0 += __shfl_xor_sync(0xffffffffu, l0, 1);
    l0 += __shfl_xor_sync(0xffffffffu, l0, 2);
    l1 += __shfl_xor_sync(0xffffffffu, l1, 1);
    l1 += __shfl_xor_sync(0xffffffffu, l1, 2);

    float* red  = (float*)sm;            // 64 x 68 f32 = 17408B
    float* lred = (float*)(sm + 17408);  // 64 f32
    __syncthreads();                     // all warps done reading K smem

    const int r0 = wg * 16 + g;
    if (kh == 1) {
        #pragma unroll
        for (int j = 0; j < 8; ++j) {
            int c = 8 * j + t4 * 2;
            *(float2*)&red[r0 * 68 + c]       = make_float2(o[j][0], o[j][1]);
            *(float2*)&red[(r0 + 8) * 68 + c] = make_float2(o[j][2], o[j][3]);
        }
        if (t4 == 0) { lred[r0] = l0; lred[r0 + 8] = l1; }
    }
    __syncthreads();
    if (kh == 0) {
        float il0 = 1.f / (l0 + lred[r0]);
        float il1 = 1.f / (l1 + lred[r0 + 8]);
        const int row0 = q0 + r0;
        #pragma unroll
        for (int j = 0; j < 8; ++j) {
            int c = 8 * j + t4 * 2;
            float2 a = *(float2*)&red[r0 * 68 + c];
            float2 d = *(float2*)&red[(r0 + 8) * 68 + c];
            float* d0 = out + ((size_t)b * SEQ + row0) * HD + c;
            *(float2*)d0 = make_float2((o[j][0] + a.x) * il0, (o[j][1] + a.y) * il0);
            *(float2*)(d0 + 8 * HD) =
                make_float2((o[j][2] + d.x) * il1, (o[j][3] + d.y) * il1);
        }
    }
}

// ---------------------------------------------------------------------------
extern "C" void kernel_launch(void* const* d_in, const int* in_sizes, int n_in,
                              void* d_out, int out_size) {
    const float* x  = (const float*)d_in[0];
    const float* Wq = (const float*)d_in[1];
    const float* Wk = (const float*)d_in[2];
    // d_in[3] (Wv) is an unused parameter in the reference model.

    __half* wh;
    cudaGetSymbolAddress((void**)&wh, g_Wh);

    round_kernel<<<64, 256>>>(Wq, wh, HD * EMBED / 4);
    round_kernel<<<64, 256>>>(Wk, wh + 64 * EMBED, HD * EMBED / 4);

    const int proj_smem = 98304;                // Xf 48K + Xh 32K + W 16K
    cudaFuncSetAttribute(proj_kernel, cudaFuncAttributeMaxDynamicSharedMemorySize,
                         proj_smem);
    proj_kernel<<<2 * (MTOT / 128), 256, proj_smem>>>(x);

    const int attn_smem = 8192 + 3 * 16384;     // 56KB -> 2 CTAs/SM, 16 warps
    cudaFuncSetAttribute(attn_kernel, cudaFuncAttributeMaxDynamicSharedMemorySize,
                         attn_smem);
    attn_kernel<<<256, 256, attn_smem>>>((float*)d_out);
}